// round 2
// baseline (speedup 1.0000x reference)
#include <cuda_runtime.h>
#include <math.h>
#include <stdint.h>

#define Bsz 8192
#define Tt  128
#define Ef  128
#define Hh  128
#define Gg  512
#define Do  5

// ---------------- device scratch (static: no allocations allowed) ----------------
// gates_x for t in [0,64) and [64,128): each 64*8192*512 floats = 1 GB
__device__ float g_gx0[64 * 8192 * 512];
__device__ float g_gx1[64 * 8192 * 512];
__device__ float g_h[Bsz * Hh];
__device__ float g_c[Bsz * Hh];
__device__ float g_gates[Bsz * Gg];
__device__ float g_y[(size_t)Tt * Bsz * Do];     // 20 MB, pre-BN outputs
__device__ float g_s[Tt * Ef * 3];               // folded emb-BN affine coeffs
__device__ float g_ymean[Tt * Do];
__device__ float g_yrstd[Tt * Do];

// ---------------- K0: zero h, c ----------------
__global__ void k_zero_hc() {
    int i = blockIdx.x * 256 + threadIdx.x;
    if (i < Bsz * Hh) { g_h[i] = 0.0f; g_c[i] = 0.0f; }
}

// ---------------- K1: per-t emb BN stats via exact x-moments ----------------
// z = x0*W0 + x1*W1 + b is linear in x, so mean/var of z over the batch are
// exact bilinear forms of the 5 batch moments of (x0, x1).
__global__ void k_emb_stats(const float* __restrict__ x,
                            const float* __restrict__ W_emb,
                            const float* __restrict__ b_emb,
                            const float* __restrict__ gamma,
                            const float* __restrict__ beta) {
    int t = blockIdx.x;
    int tid = threadIdx.x;
    float m0 = 0.f, m1 = 0.f, m00 = 0.f, m11 = 0.f, m01 = 0.f;
    for (int b = tid; b < Bsz; b += 256) {
        size_t xi = ((size_t)b * Tt + t) * 2;
        float x0 = x[xi], x1 = x[xi + 1];
        m0 += x0; m1 += x1; m00 += x0 * x0; m11 += x1 * x1; m01 += x0 * x1;
    }
    const unsigned FULL = 0xffffffffu;
    #pragma unroll
    for (int off = 16; off; off >>= 1) {
        m0  += __shfl_xor_sync(FULL, m0,  off);
        m1  += __shfl_xor_sync(FULL, m1,  off);
        m00 += __shfl_xor_sync(FULL, m00, off);
        m11 += __shfl_xor_sync(FULL, m11, off);
        m01 += __shfl_xor_sync(FULL, m01, off);
    }
    __shared__ float sw[8][5];
    __shared__ float mom[5];
    int warp = tid >> 5, lane = tid & 31;
    if (lane == 0) {
        sw[warp][0] = m0; sw[warp][1] = m1; sw[warp][2] = m00;
        sw[warp][3] = m11; sw[warp][4] = m01;
    }
    __syncthreads();
    if (tid < 5) {
        float s = 0.f;
        #pragma unroll
        for (int w = 0; w < 8; w++) s += sw[w][tid];
        mom[tid] = s * (1.0f / Bsz);
    }
    __syncthreads();
    if (tid < Ef) {
        float mx0 = mom[0], mx1 = mom[1];
        float vx0 = mom[2] - mx0 * mx0;
        float vx1 = mom[3] - mx1 * mx1;
        float cxy = mom[4] - mx0 * mx1;
        float w0 = W_emb[tid * 2], w1 = W_emb[tid * 2 + 1];
        float mu  = w0 * mx0 + w1 * mx1 + b_emb[tid];
        float var = w0 * w0 * vx0 + 2.0f * w0 * w1 * cxy + w1 * w1 * vx1;
        float rstd = rsqrtf(var + 1e-5f);
        float gr = gamma[tid] * rstd;
        int o = (t * Ef + tid) * 3;
        g_s[o + 0] = gr * w0;
        g_s[o + 1] = gr * w1;
        g_s[o + 2] = gr * (b_emb[tid] - mu) + beta[tid];
    }
}

// ---------------- K2: gates_x = relu(BN(emb)) @ W_ih^T + b_ih  (parallel) ----------
// Tile 128(M) x 64(N), K=128 fully resident. e computed on the fly from x + g_s.
#define SMEM_GX_FLOATS (16384 + 128 * 65 + 256 + 384)
__global__ void k_gx_gemm(const float* __restrict__ x,
                          const float* __restrict__ W_ih,
                          const float* __restrict__ b_ih) {
    extern __shared__ float sm[];
    float* As = sm;                       // [k=128][r=128]
    float* Bs = sm + 16384;               // [k=128][c=64] pad 65
    float* xs = sm + 16384 + 128 * 65;    // [128][2]
    float* ss = xs + 256;                 // [128][3]
    int tid = threadIdx.x;
    int t  = blockIdx.y >> 6;
    int b0 = (blockIdx.y & 63) << 7;
    int n0 = blockIdx.x << 6;

    if (tid < 128) {
        size_t xi = ((size_t)(b0 + tid) * Tt + t) * 2;
        xs[tid * 2]     = x[xi];
        xs[tid * 2 + 1] = x[xi + 1];
        int o = (t * Ef + tid) * 3;
        ss[tid * 3]     = g_s[o];
        ss[tid * 3 + 1] = g_s[o + 1];
        ss[tid * 3 + 2] = g_s[o + 2];
    }
    __syncthreads();
    for (int idx = tid; idx < 128 * 128; idx += 256) {
        int j = idx >> 7, r = idx & 127;
        float e = fmaf(ss[j * 3], xs[r * 2], fmaf(ss[j * 3 + 1], xs[r * 2 + 1], ss[j * 3 + 2]));
        As[j * 128 + r] = fmaxf(e, 0.0f);
    }
    for (int idx = tid; idx < 128 * 64; idx += 256) {
        int k = idx & 127, c = idx >> 7;
        Bs[k * 65 + c] = W_ih[(size_t)(n0 + c) * Ef + k];
    }
    __syncthreads();

    int r0 = (tid >> 4) << 3;
    int c0 = (tid & 15) << 2;
    float acc[8][4];
    #pragma unroll
    for (int i = 0; i < 8; i++)
        #pragma unroll
        for (int j = 0; j < 4; j++) acc[i][j] = 0.0f;

    #pragma unroll 4
    for (int k = 0; k < 128; k++) {
        float4 a0 = *(const float4*)&As[k * 128 + r0];
        float4 a1 = *(const float4*)&As[k * 128 + r0 + 4];
        float av[8] = {a0.x, a0.y, a0.z, a0.w, a1.x, a1.y, a1.z, a1.w};
        float bv[4];
        #pragma unroll
        for (int j = 0; j < 4; j++) bv[j] = Bs[k * 65 + c0 + j];
        #pragma unroll
        for (int i = 0; i < 8; i++)
            #pragma unroll
            for (int j = 0; j < 4; j++) acc[i][j] = fmaf(av[i], bv[j], acc[i][j]);
    }

    float4 bia = *(const float4*)&b_ih[n0 + c0];
    float* gx = (t < 64) ? g_gx0 : g_gx1;
    size_t tb = (size_t)(t & 63) * Bsz;
    #pragma unroll
    for (int i = 0; i < 8; i++) {
        size_t o = (tb + b0 + r0 + i) * Gg + n0 + c0;
        float4 v = make_float4(acc[i][0] + bia.x, acc[i][1] + bia.y,
                               acc[i][2] + bia.z, acc[i][3] + bia.w);
        *(float4*)&gx[o] = v;
    }
}

// ---------------- K3: per-step recurrent GEMM: gates = h@W_hh^T + b_hh + gates_x[t] --
#define SMEM_REC_FLOATS (128 * 129 + 128 * 65)
__global__ void k_rec_gemm(const float* __restrict__ W_hh,
                           const float* __restrict__ b_hh, int t) {
    extern __shared__ float sm[];
    float* As = sm;                 // [k=128][r=128] pad 129
    float* Bs = sm + 128 * 129;     // [k=128][c=64] pad 65
    int tid = threadIdx.x;
    int b0 = blockIdx.y << 7;
    int n0 = blockIdx.x << 6;

    for (int idx = tid; idx < 128 * 128; idx += 256) {
        int k = idx & 127, r = idx >> 7;
        As[k * 129 + r] = g_h[(size_t)(b0 + r) * Hh + k];
    }
    for (int idx = tid; idx < 128 * 64; idx += 256) {
        int k = idx & 127, c = idx >> 7;
        Bs[k * 65 + c] = W_hh[(size_t)(n0 + c) * Hh + k];
    }
    __syncthreads();

    int r0 = (tid >> 4) << 3;
    int c0 = (tid & 15) << 2;
    float acc[8][4];
    #pragma unroll
    for (int i = 0; i < 8; i++)
        #pragma unroll
        for (int j = 0; j < 4; j++) acc[i][j] = 0.0f;

    #pragma unroll 4
    for (int k = 0; k < 128; k++) {
        float av[8], bv[4];
        #pragma unroll
        for (int i = 0; i < 8; i++) av[i] = As[k * 129 + r0 + i];
        #pragma unroll
        for (int j = 0; j < 4; j++) bv[j] = Bs[k * 65 + c0 + j];
        #pragma unroll
        for (int i = 0; i < 8; i++)
            #pragma unroll
            for (int j = 0; j < 4; j++) acc[i][j] = fmaf(av[i], bv[j], acc[i][j]);
    }

    const float* gx = (t < 64) ? g_gx0 : g_gx1;
    size_t tb = (size_t)(t & 63) * Bsz;
    float4 bh = *(const float4*)&b_hh[n0 + c0];
    #pragma unroll
    for (int i = 0; i < 8; i++) {
        int row = b0 + r0 + i;
        float4 gv = *(const float4*)&gx[(tb + row) * Gg + n0 + c0];
        float4 v = make_float4(acc[i][0] + bh.x + gv.x, acc[i][1] + bh.y + gv.y,
                               acc[i][2] + bh.z + gv.z, acc[i][3] + bh.w + gv.w);
        *(float4*)&g_gates[(size_t)row * Gg + n0 + c0] = v;
    }
}

// ---------------- K4: LSTM cell + fused y = h@W_out^T (pre-BN; b_out cancels) -------
__global__ void k_cell(const float* __restrict__ W_out, int t) {
    int b = blockIdx.x;
    int j = threadIdx.x;  // 128
    __shared__ float Ws[Do * Hh];
    __shared__ float part[4][Do];
    for (int i = j; i < Do * Hh; i += 128) Ws[i] = W_out[i];

    size_t gb = (size_t)b * Gg;
    float ig = g_gates[gb + j];
    float fg = g_gates[gb + Hh + j];
    float gg = g_gates[gb + 2 * Hh + j];
    float og = g_gates[gb + 3 * Hh + j];
    float c  = g_c[b * Hh + j];
    __syncthreads();

    float si = 1.0f / (1.0f + expf(-ig));
    float sf = 1.0f / (1.0f + expf(-fg));
    float so = 1.0f / (1.0f + expf(-og));
    float cn = sf * c + si * tanhf(gg);
    float hn = so * tanhf(cn);
    g_c[b * Hh + j] = cn;
    g_h[b * Hh + j] = hn;

    const unsigned FULL = 0xffffffffu;
    #pragma unroll
    for (int f = 0; f < Do; f++) {
        float v = hn * Ws[f * Hh + j];
        #pragma unroll
        for (int off = 16; off; off >>= 1) v += __shfl_xor_sync(FULL, v, off);
        if ((j & 31) == 0) part[j >> 5][f] = v;
    }
    __syncthreads();
    if (j < Do) {
        float s = part[0][j] + part[1][j] + part[2][j] + part[3][j];
        g_y[((size_t)t * Bsz + b) * Do + j] = s;
    }
}

// ---------------- K5: per-(t, f) output BN stats ----------------
__global__ void k_ystats() {
    int tf = blockIdx.x;
    int t = tf / Do, f = tf % Do;
    int tid = threadIdx.x;
    float s = 0.f, q = 0.f;
    for (int b = tid; b < Bsz; b += 256) {
        float v = g_y[((size_t)t * Bsz + b) * Do + f];
        s += v; q += v * v;
    }
    const unsigned FULL = 0xffffffffu;
    #pragma unroll
    for (int off = 16; off; off >>= 1) {
        s += __shfl_xor_sync(FULL, s, off);
        q += __shfl_xor_sync(FULL, q, off);
    }
    __shared__ float sws[8], swq[8];
    int warp = tid >> 5, lane = tid & 31;
    if (lane == 0) { sws[warp] = s; swq[warp] = q; }
    __syncthreads();
    if (tid == 0) {
        float S = 0.f, Q = 0.f;
        #pragma unroll
        for (int w = 0; w < 8; w++) { S += sws[w]; Q += swq[w]; }
        float mean = S * (1.0f / Bsz);
        float var = Q * (1.0f / Bsz) - mean * mean;
        g_ymean[t * Do + f] = mean;
        g_yrstd[t * Do + f] = rsqrtf(var + 1e-5f);
    }
}

// ---------------- K6: normalize y -> out[b, t, f] ----------------
__global__ void k_ynorm(const float* __restrict__ gamma,
                        const float* __restrict__ beta,
                        float* __restrict__ out) {
    size_t i = (size_t)blockIdx.x * 256 + threadIdx.x;
    if (i >= (size_t)Bsz * Tt * Do) return;
    int f = (int)(i % Do);
    size_t bt = i / Do;
    int t = (int)(bt % Tt);
    size_t b = bt / Tt;
    float m = g_ymean[t * Do + f], r = g_yrstd[t * Do + f];
    float v = g_y[((size_t)t * Bsz + b) * Do + f];
    out[i] = gamma[f] * (v - m) * r + beta[f];
}

// ---------------- K7: final h, c -> out tail ----------------
__global__ void k_copy_hc(float* __restrict__ out) {
    int i = blockIdx.x * 256 + threadIdx.x;
    if (i < Bsz * Hh) {
        const size_t OFF_H = (size_t)Bsz * Tt * Do;
        out[OFF_H + i] = g_h[i];
        out[OFF_H + Bsz * Hh + i] = g_c[i];
    }
}

// ---------------- launch ----------------
extern "C" void kernel_launch(void* const* d_in, const int* in_sizes, int n_in,
                              void* d_out, int out_size) {
    const float* x         = (const float*)d_in[0];
    const float* W_emb     = (const float*)d_in[1];
    const float* b_emb     = (const float*)d_in[2];
    const float* gamma_emb = (const float*)d_in[3];
    const float* beta_emb  = (const float*)d_in[4];
    const float* W_ih      = (const float*)d_in[5];
    const float* b_ih      = (const float*)d_in[6];
    const float* W_hh      = (const float*)d_in[7];
    const float* b_hh      = (const float*)d_in[8];
    const float* W_out     = (const float*)d_in[9];
    // d_in[10] = b_out: cancels exactly inside the output BatchNorm.
    const float* gamma_out = (const float*)d_in[11];
    const float* beta_out  = (const float*)d_in[12];
    float* out = (float*)d_out;

    const int SMEM_GX  = SMEM_GX_FLOATS * 4;
    const int SMEM_REC = SMEM_REC_FLOATS * 4;
    cudaFuncSetAttribute(k_gx_gemm,  cudaFuncAttributeMaxDynamicSharedMemorySize, SMEM_GX);
    cudaFuncSetAttribute(k_rec_gemm, cudaFuncAttributeMaxDynamicSharedMemorySize, SMEM_REC);

    k_zero_hc<<<(Bsz * Hh + 255) / 256, 256>>>();
    k_emb_stats<<<Tt, 256>>>(x, W_emb, b_emb, gamma_emb, beta_emb);
    k_gx_gemm<<<dim3(8, 8192), 256, SMEM_GX>>>(x, W_ih, b_ih);

    for (int t = 0; t < Tt; t++) {
        k_rec_gemm<<<dim3(8, 64), 256, SMEM_REC>>>(W_hh, b_hh, t);
        k_cell<<<Bsz, 128>>>(W_out, t);
    }

    k_ystats<<<Tt * Do, 256>>>();
    int n6 = Bsz * Tt * Do;
    k_ynorm<<<(n6 + 255) / 256, 256>>>(gamma_out, beta_out, out);
    k_copy_hc<<<(Bsz * Hh + 255) / 256, 256>>>(out);
}

// round 4
// speedup vs baseline: 1.7381x; 1.7381x over previous
#include <cuda_runtime.h>
#include <cuda_bf16.h>
#include <math.h>
#include <stdint.h>

#define Bsz 8192
#define Tt  128
#define Do  5
#define OFF_H ((size_t)Bsz * Tt * Do)
#define OFF_C (OFF_H + (size_t)Bsz * 128)

// ---------------- device scratch ----------------
__device__ float g_gx0[64 * 8192 * 512];           // gates_x t<64  [t][row][n']
__device__ float g_gx1[64 * 8192 * 512];           // gates_x t>=64
__device__ float g_c[(size_t)Bsz * 128];           // c state [row][j]
__device__ float g_ypart[(size_t)4 * 640 * 8192];  // y partials [nc][t*5+f][row]
__device__ float g_s[Tt * 128 * 3];                // folded emb-BN affine
__device__ float g_bias[512];                      // b_ih+b_hh permuted to n'
__device__ float g_ymean[Tt * Do];
__device__ float g_yrstd[Tt * Do];
// bf16 operand images, row-major 256B rows with 16B-chunk XOR swizzle
__device__ __align__(16) char g_wih_h[512 * 256];
__device__ __align__(16) char g_wih_l[512 * 256];
__device__ __align__(16) char g_whh_h[512 * 256];
__device__ __align__(16) char g_whh_l[512 * 256];
__device__ __align__(16) char g_himg[2][2][8192 * 256];  // [parity][hi/lo]

// swizzled byte offset of 16B chunk kc in row
__device__ __forceinline__ int swz(int row, int kc) {
    return row * 256 + ((kc ^ (row & 7)) << 4);
}
__device__ __forceinline__ uint32_t s2u(const void* p) {
    uint32_t a;
    asm("{ .reg .u64 t; cvta.to.shared.u64 t, %1; cvt.u32.u64 %0, t; }" : "=r"(a) : "l"(p));
    return a;
}
__device__ __forceinline__ void ldsm4(uint32_t r[4], uint32_t a) {
    asm volatile("ldmatrix.sync.aligned.m8n8.x4.shared.b16 {%0,%1,%2,%3}, [%4];"
        : "=r"(r[0]), "=r"(r[1]), "=r"(r[2]), "=r"(r[3]) : "r"(a));
}
__device__ __forceinline__ void mma16816(float d[4], const uint32_t a[4], uint32_t b0, uint32_t b1) {
    asm volatile("mma.sync.aligned.m16n8k16.row.col.f32.bf16.bf16.f32 "
        "{%0,%1,%2,%3}, {%4,%5,%6,%7}, {%8,%9}, {%0,%1,%2,%3};"
        : "+f"(d[0]), "+f"(d[1]), "+f"(d[2]), "+f"(d[3])
        : "r"(a[0]), "r"(a[1]), "r"(a[2]), "r"(a[3]), "r"(b0), "r"(b1));
}
__device__ __forceinline__ uint32_t pkbf(float a, float b) {
    __nv_bfloat16 ha = __float2bfloat16(a), hb = __float2bfloat16(b);
    return (uint32_t)__bfloat16_as_ushort(ha) | ((uint32_t)__bfloat16_as_ushort(hb) << 16);
}

// 3-pass hi/lo bf16 GEMM: warp tile 64x32, frags m4 x n4, K=128
__device__ __forceinline__ void gemm3pass(uint32_t Ah, uint32_t Al, uint32_t Bh, uint32_t Bl,
                                          int wm0, int wn0, int lane, float acc[4][4][4]) {
    int ar  = (lane & 7) | (((lane >> 3) & 1) << 3);
    int akc = lane >> 4;
    int rbA[4], rxA[4];
    #pragma unroll
    for (int mf = 0; mf < 4; mf++) {
        int r = wm0 + mf * 16 + ar;
        rbA[mf] = r * 256; rxA[mf] = r & 7;
    }
    int bnh = (lane >> 4) & 1, bkc = (lane >> 3) & 1;
    int rbB[2], rxB[2];
    #pragma unroll
    for (int p = 0; p < 2; p++) {
        int r = wn0 + p * 16 + bnh * 8 + (lane & 7);
        rbB[p] = r * 256; rxB[p] = r & 7;
    }
    #pragma unroll
    for (int pass = 0; pass < 3; pass++) {
        uint32_t Ab = (pass == 1) ? Al : Ah;
        uint32_t Bb = (pass == 2) ? Bl : Bh;
        #pragma unroll
        for (int ks = 0; ks < 8; ks++) {
            int kc2 = ks << 1;
            uint32_t a[4][4], b[2][4];
            #pragma unroll
            for (int mf = 0; mf < 4; mf++)
                ldsm4(a[mf], Ab + rbA[mf] + (((kc2 + akc) ^ rxA[mf]) << 4));
            #pragma unroll
            for (int p = 0; p < 2; p++)
                ldsm4(b[p], Bb + rbB[p] + (((kc2 + bkc) ^ rxB[p]) << 4));
            #pragma unroll
            for (int mf = 0; mf < 4; mf++)
                #pragma unroll
                for (int nf = 0; nf < 4; nf++)
                    mma16816(acc[mf][nf], a[mf], b[nf >> 1][(nf & 1) * 2], b[nf >> 1][(nf & 1) * 2 + 1]);
        }
    }
}
// store fragments to staged D [rows][stride 132]
__device__ __forceinline__ void stageD(float* Dst, float acc[4][4][4], int wm0, int wn0, int lane) {
    int rr = lane >> 2, cc = (lane & 3) << 1;
    #pragma unroll
    for (int mf = 0; mf < 4; mf++)
        #pragma unroll
        for (int nf = 0; nf < 4; nf++) {
            int r = wm0 + mf * 16 + rr, c = wn0 + nf * 8 + cc;
            *(float2*)&Dst[r * 132 + c]       = make_float2(acc[mf][nf][0], acc[mf][nf][1]);
            *(float2*)&Dst[(r + 8) * 132 + c] = make_float2(acc[mf][nf][2], acc[mf][nf][3]);
        }
}

// ---------------- K1: per-t emb BN stats via exact x-moments ----------------
__global__ void k_emb_stats(const float* __restrict__ x, const float* __restrict__ W_emb,
                            const float* __restrict__ b_emb, const float* __restrict__ gamma,
                            const float* __restrict__ beta) {
    int t = blockIdx.x, tid = threadIdx.x;
    float m0 = 0.f, m1 = 0.f, m00 = 0.f, m11 = 0.f, m01 = 0.f;
    for (int b = tid; b < Bsz; b += 256) {
        size_t xi = ((size_t)b * Tt + t) * 2;
        float x0 = x[xi], x1 = x[xi + 1];
        m0 += x0; m1 += x1; m00 += x0 * x0; m11 += x1 * x1; m01 += x0 * x1;
    }
    const unsigned F = 0xffffffffu;
    #pragma unroll
    for (int o = 16; o; o >>= 1) {
        m0 += __shfl_xor_sync(F, m0, o); m1 += __shfl_xor_sync(F, m1, o);
        m00 += __shfl_xor_sync(F, m00, o); m11 += __shfl_xor_sync(F, m11, o);
        m01 += __shfl_xor_sync(F, m01, o);
    }
    __shared__ float sw[8][5], mom[5];
    int w = tid >> 5, l = tid & 31;
    if (l == 0) { sw[w][0] = m0; sw[w][1] = m1; sw[w][2] = m00; sw[w][3] = m11; sw[w][4] = m01; }
    __syncthreads();
    if (tid < 5) {
        float s = 0.f;
        #pragma unroll
        for (int i = 0; i < 8; i++) s += sw[i][tid];
        mom[tid] = s * (1.0f / Bsz);
    }
    __syncthreads();
    if (tid < 128) {
        float mx0 = mom[0], mx1 = mom[1];
        float vx0 = mom[2] - mx0 * mx0, vx1 = mom[3] - mx1 * mx1, cxy = mom[4] - mx0 * mx1;
        float w0 = W_emb[tid * 2], w1 = W_emb[tid * 2 + 1];
        float mu = w0 * mx0 + w1 * mx1 + b_emb[tid];
        float var = w0 * w0 * vx0 + 2.0f * w0 * w1 * cxy + w1 * w1 * vx1;
        float gr = gamma[tid] * rsqrtf(var + 1e-5f);
        int o = (t * 128 + tid) * 3;
        g_s[o] = gr * w0; g_s[o + 1] = gr * w1;
        g_s[o + 2] = gr * (b_emb[tid] - mu) + beta[tid];
    }
}

// ---------------- K2: build bf16 hi/lo weight images (n' = 4j+gate) ----------------
__global__ void k_prep(const float* __restrict__ Wih, const float* __restrict__ Whh,
                       const float* __restrict__ bih, const float* __restrict__ bhh) {
    int id = blockIdx.x * 256 + threadIdx.x;  // 131072
    int mat = id >> 16, e = id & 65535;
    int np = e >> 7, k = e & 127;
    int src = ((np & 3) * 128 + (np >> 2)) * 128 + k;
    float wv = mat ? Whh[src] : Wih[src];
    __nv_bfloat16 hi = __float2bfloat16(wv);
    __nv_bfloat16 lo = __float2bfloat16(wv - __bfloat162float(hi));
    int off = np * 256 + (((k >> 3) ^ (np & 7)) << 4) + (k & 7) * 2;
    *(__nv_bfloat16*)((mat ? g_whh_h : g_wih_h) + off) = hi;
    *(__nv_bfloat16*)((mat ? g_whh_l : g_wih_l) + off) = lo;
    if (id < 512) {
        int orig = (id & 3) * 128 + (id >> 2);
        g_bias[id] = bih[orig] + bhh[orig];
    }
}

// ---------------- K3: gates_x = relu(BN(emb)) @ W_ih^T + biases ----------------
// block: (t, mtile 128 rows, nchunk 128 cols), 256 thr
#define GX_AH 0
#define GX_AL 32768
#define GX_BH 65536
#define GX_BL 98304
#define GX_DST 131072
#define GX_SS 198656
#define GX_SMEM (198656 + 1536)
__global__ void __launch_bounds__(256, 1) k_gx(const float* __restrict__ x) {
    extern __shared__ char sm[];
    float* Dst = (float*)(sm + GX_DST);
    float* ss = (float*)(sm + GX_SS);
    int tid = threadIdx.x;
    int nc = blockIdx.x & 3, m = blockIdx.x >> 2, t = blockIdx.y;
    int b0 = m << 7;
    uint32_t smb = s2u(sm);
    for (int i = tid; i < 384; i += 256) ss[i] = g_s[t * 384 + i];
    {
        const uint4* bh = (const uint4*)(g_wih_h + nc * 128 * 256);
        const uint4* bl = (const uint4*)(g_wih_l + nc * 128 * 256);
        uint4* dh = (uint4*)(sm + GX_BH);
        uint4* dl = (uint4*)(sm + GX_BL);
        for (int i = tid; i < 2048; i += 256) { dh[i] = bh[i]; dl[i] = bl[i]; }
    }
    __syncthreads();
    {   // build e images: row = tid>>1, k half = (tid&1)*64
        int row = tid >> 1, kh = tid & 1;
        size_t xi = ((size_t)(b0 + row) * Tt + t) * 2;
        float x0 = x[xi], x1 = x[xi + 1];
        #pragma unroll
        for (int ch = 0; ch < 8; ch++) {
            uint32_t wh[4], wl[4];
            #pragma unroll
            for (int q = 0; q < 4; q++) {
                int k = kh * 64 + ch * 8 + q * 2;
                float e0 = fmaxf(fmaf(ss[k * 3], x0, fmaf(ss[k * 3 + 1], x1, ss[k * 3 + 2])), 0.f);
                float e1 = fmaxf(fmaf(ss[k * 3 + 3], x0, fmaf(ss[k * 3 + 4], x1, ss[k * 3 + 5])), 0.f);
                __nv_bfloat16 h0 = __float2bfloat16(e0), h1 = __float2bfloat16(e1);
                float r0 = e0 - __bfloat162float(h0), r1 = e1 - __bfloat162float(h1);
                wh[q] = (uint32_t)__bfloat16_as_ushort(h0) | ((uint32_t)__bfloat16_as_ushort(h1) << 16);
                wl[q] = pkbf(r0, r1);
            }
            int off = swz(row, kh * 8 + ch);
            *(uint4*)(sm + GX_AH + off) = make_uint4(wh[0], wh[1], wh[2], wh[3]);
            *(uint4*)(sm + GX_AL + off) = make_uint4(wl[0], wl[1], wl[2], wl[3]);
        }
    }
    __syncthreads();
    float acc[4][4][4];
    #pragma unroll
    for (int i = 0; i < 4; i++)
        #pragma unroll
        for (int j = 0; j < 4; j++)
            #pragma unroll
            for (int q = 0; q < 4; q++) acc[i][j][q] = 0.f;
    int lane = tid & 31, w = tid >> 5;
    int wm0 = (w >> 2) * 64, wn0 = (w & 3) * 32;
    gemm3pass(smb + GX_AH, smb + GX_AL, smb + GX_BH, smb + GX_BL, wm0, wn0, lane, acc);
    stageD(Dst, acc, wm0, wn0, lane);
    __syncthreads();
    float* gx = (t < 64 ? g_gx0 : g_gx1) + ((size_t)(t & 63) * 8192 + b0) * 512 + nc * 128;
    #pragma unroll
    for (int it = 0; it < 16; it++) {
        int idx4 = tid + it * 256;
        int row = idx4 >> 5, c4 = (idx4 & 31) << 2;
        float4 v = *(float4*)&Dst[row * 132 + c4];
        float4 bv = *(const float4*)&g_bias[nc * 128 + c4];
        v.x += bv.x; v.y += bv.y; v.z += bv.z; v.w += bv.w;
        *(float4*)&gx[(size_t)row * 512 + c4] = v;
    }
}

// ---------------- K4: one fused step: h@W_hh MMA + gx + LSTM cell + y + h repack ----
// grid (nc=4, mtile=32), 512 thr, tile M=256 x N=128
#define ST_AH 0
#define ST_AL 65536
#define ST_BH 131072
#define ST_BL 163840
#define ST_WS 196608
#define ST_SMEM (196608 + 2560)
__global__ void __launch_bounds__(512, 1) k_step(int t, const float* __restrict__ Wout,
                                                 float* __restrict__ out) {
    extern __shared__ char sm[];
    float* Dst = (float*)sm;  // aliases A/B after mma, stride 132
    float* Ws = (float*)(sm + ST_WS);
    int tid = threadIdx.x;
    int nc = blockIdx.x, m = blockIdx.y, b0 = m << 8;
    uint32_t smb = s2u(sm);
    for (int i = tid; i < 640; i += 512) Ws[i] = Wout[i];
    if (t > 0) {
        int p = t & 1;
        const uint4* ah = (const uint4*)(g_himg[p][0] + (size_t)b0 * 256);
        const uint4* al = (const uint4*)(g_himg[p][1] + (size_t)b0 * 256);
        uint4* da = (uint4*)(sm + ST_AH);
        uint4* dl = (uint4*)(sm + ST_AL);
        for (int i = tid; i < 4096; i += 512) { da[i] = ah[i]; dl[i] = al[i]; }
        const uint4* bh = (const uint4*)(g_whh_h + nc * 128 * 256);
        const uint4* bl = (const uint4*)(g_whh_l + nc * 128 * 256);
        uint4* eb = (uint4*)(sm + ST_BH);
        uint4* el = (uint4*)(sm + ST_BL);
        for (int i = tid; i < 2048; i += 512) { eb[i] = bh[i]; el[i] = bl[i]; }
        __syncthreads();
        float acc[4][4][4];
        #pragma unroll
        for (int i = 0; i < 4; i++)
            #pragma unroll
            for (int j = 0; j < 4; j++)
                #pragma unroll
                for (int q = 0; q < 4; q++) acc[i][j][q] = 0.f;
        int lane = tid & 31, w = tid >> 5;
        int wm0 = (w >> 2) * 64, wn0 = (w & 3) * 32;
        gemm3pass(smb + ST_AH, smb + ST_AL, smb + ST_BH, smb + ST_BL, wm0, wn0, lane, acc);
        __syncthreads();  // everyone done reading A/B before Dst alias write
        stageD(Dst, acc, wm0, wn0, lane);
    }
    __syncthreads();
    const float* gx = (t < 64 ? g_gx0 : g_gx1) + ((size_t)(t & 63) * 8192 + b0) * 512 + nc * 128;
    #pragma unroll
    for (int it = 0; it < 16; it++) {
        int idx4 = tid + it * 512;
        int row = idx4 >> 5, c4 = (idx4 & 31) << 2;
        float4 gv = *(const float4*)&gx[(size_t)row * 512 + c4];
        if (t > 0) {
            float4 d = *(float4*)&Dst[row * 132 + c4];
            gv.x += d.x; gv.y += d.y; gv.z += d.z; gv.w += d.w;
        }
        *(float4*)&Dst[row * 132 + c4] = gv;
    }
    __syncthreads();
    // cell: thread -> (row = tid>>1, 16 j's at jh*16)
    int row = tid >> 1, jh = tid & 1;
    int rg = b0 + row;
    int jg0 = nc * 32 + jh * 16;
    float cold[16];
    if (t > 0) {
        #pragma unroll
        for (int q = 0; q < 4; q++)
            *(float4*)&cold[q * 4] = *(const float4*)&g_c[(size_t)rg * 128 + jg0 + q * 4];
    } else {
        #pragma unroll
        for (int q = 0; q < 16; q++) cold[q] = 0.f;
    }
    float y0 = 0.f, y1 = 0.f, y2 = 0.f, y3 = 0.f, y4 = 0.f;
    float hnv[16], cnv[16];
    unsigned short hs[16], lsv[16];
    #pragma unroll
    for (int jj = 0; jj < 16; jj++) {
        int jloc = jh * 16 + jj;
        float4 g4 = *(float4*)&Dst[row * 132 + (jloc << 2)];
        float si = __fdividef(1.f, 1.f + __expf(-g4.x));
        float sf = __fdividef(1.f, 1.f + __expf(-g4.y));
        float tg = __fdividef(2.f, 1.f + __expf(-2.f * g4.z)) - 1.f;
        float so = __fdividef(1.f, 1.f + __expf(-g4.w));
        float cn = sf * cold[jj] + si * tg;
        float tc = __fdividef(2.f, 1.f + __expf(-2.f * cn)) - 1.f;
        float hn = so * tc;
        cnv[jj] = cn; hnv[jj] = hn;
        __nv_bfloat16 hb = __float2bfloat16(hn);
        hs[jj] = __bfloat16_as_ushort(hb);
        lsv[jj] = __bfloat16_as_ushort(__float2bfloat16(hn - __bfloat162float(hb)));
        int jg = jg0 + jj;
        y0 = fmaf(hn, Ws[jg], y0);
        y1 = fmaf(hn, Ws[128 + jg], y1);
        y2 = fmaf(hn, Ws[256 + jg], y2);
        y3 = fmaf(hn, Ws[384 + jg], y3);
        y4 = fmaf(hn, Ws[512 + jg], y4);
    }
    #pragma unroll
    for (int q = 0; q < 4; q++)
        *(float4*)&g_c[(size_t)rg * 128 + jg0 + q * 4] = *(float4*)&cnv[q * 4];
    // pack h image for next step, parity (t&1)^1
    int p1 = (t & 1) ^ 1;
    #pragma unroll
    for (int ch = 0; ch < 2; ch++) {
        uint32_t wh[4], wl[4];
        #pragma unroll
        for (int q = 0; q < 4; q++) {
            wh[q] = (uint32_t)hs[ch * 8 + q * 2] | ((uint32_t)hs[ch * 8 + q * 2 + 1] << 16);
            wl[q] = (uint32_t)lsv[ch * 8 + q * 2] | ((uint32_t)lsv[ch * 8 + q * 2 + 1] << 16);
        }
        int off = swz(rg, (jg0 >> 3) + ch);
        *(uint4*)(g_himg[p1][0] + off) = make_uint4(wh[0], wh[1], wh[2], wh[3]);
        *(uint4*)(g_himg[p1][1] + off) = make_uint4(wl[0], wl[1], wl[2], wl[3]);
    }
    const unsigned F = 0xffffffffu;
    y0 += __shfl_xor_sync(F, y0, 1); y1 += __shfl_xor_sync(F, y1, 1);
    y2 += __shfl_xor_sync(F, y2, 1); y3 += __shfl_xor_sync(F, y3, 1);
    y4 += __shfl_xor_sync(F, y4, 1);
    if (!jh) {
        size_t yb = ((size_t)nc * 640 + t * 5) * 8192 + rg;
        g_ypart[yb] = y0; g_ypart[yb + 8192] = y1; g_ypart[yb + 16384] = y2;
        g_ypart[yb + 24576] = y3; g_ypart[yb + 32768] = y4;
    }
    if (t == 127) {
        #pragma unroll
        for (int q = 0; q < 4; q++) {
            *(float4*)&out[OFF_H + (size_t)rg * 128 + jg0 + q * 4] = *(float4*)&hnv[q * 4];
            *(float4*)&out[OFF_C + (size_t)rg * 128 + jg0 + q * 4] = *(float4*)&cnv[q * 4];
        }
    }
}

// ---------------- K5/K6: output BN over y partials ----------------
__global__ void k_ystats() {
    int tf = blockIdx.x, tid = threadIdx.x;
    float s = 0.f, q = 0.f;
    for (int b = tid; b < Bsz; b += 256) {
        float v = g_ypart[(size_t)tf * 8192 + b]
                + g_ypart[(size_t)640 * 8192 + (size_t)tf * 8192 + b]
                + g_ypart[(size_t)2 * 640 * 8192 + (size_t)tf * 8192 + b]
                + g_ypart[(size_t)3 * 640 * 8192 + (size_t)tf * 8192 + b];
        s += v; q += v * v;
    }
    const unsigned F = 0xffffffffu;
    #pragma unroll
    for (int o = 16; o; o >>= 1) { s += __shfl_xor_sync(F, s, o); q += __shfl_xor_sync(F, q, o); }
    __shared__ float sws[8], swq[8];
    int w = tid >> 5;
    if ((tid & 31) == 0) { sws[w] = s; swq[w] = q; }
    __syncthreads();
    if (tid == 0) {
        float S = 0.f, Q = 0.f;
        #pragma unroll
        for (int i = 0; i < 8; i++) { S += sws[i]; Q += swq[i]; }
        float mean = S * (1.0f / Bsz);
        g_ymean[tf] = mean;
        g_yrstd[tf] = rsqrtf(Q * (1.0f / Bsz) - mean * mean + 1e-5f);
    }
}
__global__ void k_ynorm(const float* __restrict__ gamma, const float* __restrict__ beta,
                        float* __restrict__ out) {
    size_t i = (size_t)blockIdx.x * 256 + threadIdx.x;
    if (i >= (size_t)Bsz * Tt * Do) return;
    size_t b = i / 640;
    int r = (int)(i % 640);
    int f = r % 5;
    int tf = r;
    float v = g_ypart[(size_t)tf * 8192 + b]
            + g_ypart[(size_t)640 * 8192 + (size_t)tf * 8192 + b]
            + g_ypart[(size_t)2 * 640 * 8192 + (size_t)tf * 8192 + b]
            + g_ypart[(size_t)3 * 640 * 8192 + (size_t)tf * 8192 + b];
    out[i] = gamma[f] * (v - g_ymean[tf]) * g_yrstd[tf] + beta[f];
}

// ---------------- launch ----------------
extern "C" void kernel_launch(void* const* d_in, const int* in_sizes, int n_in,
                              void* d_out, int out_size) {
    const float* x         = (const float*)d_in[0];
    const float* W_emb     = (const float*)d_in[1];
    const float* b_emb     = (const float*)d_in[2];
    const float* gamma_emb = (const float*)d_in[3];
    const float* beta_emb  = (const float*)d_in[4];
    const float* W_ih      = (const float*)d_in[5];
    const float* b_ih      = (const float*)d_in[6];
    const float* W_hh      = (const float*)d_in[7];
    const float* b_hh      = (const float*)d_in[8];
    const float* W_out     = (const float*)d_in[9];
    // d_in[10] = b_out: cancels exactly inside the output BatchNorm.
    const float* gamma_out = (const float*)d_in[11];
    const float* beta_out  = (const float*)d_in[12];
    float* out = (float*)d_out;

    cudaFuncSetAttribute(k_gx,   cudaFuncAttributeMaxDynamicSharedMemorySize, GX_SMEM);
    cudaFuncSetAttribute(k_step, cudaFuncAttributeMaxDynamicSharedMemorySize, ST_SMEM);

    k_emb_stats<<<Tt, 256>>>(x, W_emb, b_emb, gamma_emb, beta_emb);
    k_prep<<<512, 256>>>(W_ih, W_hh, b_ih, b_hh);
    k_gx<<<dim3(256, 128), 256, GX_SMEM>>>(x);
    for (int t = 0; t < Tt; t++)
        k_step<<<dim3(4, 32), 512, ST_SMEM>>>(t, W_out, out);
    k_ystats<<<Tt * Do, 256>>>();
    int n = Bsz * Tt * Do;
    k_ynorm<<<(n + 255) / 256, 256>>>(gamma_out, beta_out, out);
}

// round 6
// speedup vs baseline: 1.7680x; 1.0172x over previous
#include <cuda_runtime.h>
#include <cuda_bf16.h>
#include <math.h>
#include <stdint.h>

#define Bsz 8192
#define Tt  128
#define Do  5
#define OFF_H ((size_t)Bsz * Tt * Do)
#define OFF_C (OFF_H + (size_t)Bsz * 128)

// ---------------- device scratch ----------------
__device__ float g_c[(size_t)Bsz * 128];           // c state [row][j]
__device__ float g_ypart[(size_t)4 * 640 * 8192];  // y partials [nc][t*5+f][row]
__device__ float g_s[Tt * 128 * 3];                // folded emb-BN affine
__device__ float g_bias[512];                      // b_ih+b_hh permuted to n'
__device__ float g_ymean[Tt * Do];
__device__ float g_yrstd[Tt * Do];
// bf16 operand images, row-major 256B rows with 16B-chunk XOR swizzle
__device__ __align__(16) char g_wih_h[512 * 256];
__device__ __align__(16) char g_wih_l[512 * 256];
__device__ __align__(16) char g_whh_h[512 * 256];
__device__ __align__(16) char g_whh_l[512 * 256];
__device__ __align__(16) char g_himg[2][2][8192 * 256];  // [parity][hi/lo]

// swizzled byte offset of 16B chunk kc in row
__device__ __forceinline__ int swz(int row, int kc) {
    return row * 256 + ((kc ^ (row & 7)) << 4);
}
__device__ __forceinline__ uint32_t s2u(const void* p) {
    uint32_t a;
    asm("{ .reg .u64 t; cvta.to.shared.u64 t, %1; cvt.u32.u64 %0, t; }" : "=r"(a) : "l"(p));
    return a;
}
__device__ __forceinline__ void ldsm4(uint32_t r[4], uint32_t a) {
    asm volatile("ldmatrix.sync.aligned.m8n8.x4.shared.b16 {%0,%1,%2,%3}, [%4];"
        : "=r"(r[0]), "=r"(r[1]), "=r"(r[2]), "=r"(r[3]) : "r"(a));
}
__device__ __forceinline__ void mma16816(float d[4], const uint32_t a[4], uint32_t b0, uint32_t b1) {
    asm volatile("mma.sync.aligned.m16n8k16.row.col.f32.bf16.bf16.f32 "
        "{%0,%1,%2,%3}, {%4,%5,%6,%7}, {%8,%9}, {%0,%1,%2,%3};"
        : "+f"(d[0]), "+f"(d[1]), "+f"(d[2]), "+f"(d[3])
        : "r"(a[0]), "r"(a[1]), "r"(a[2]), "r"(a[3]), "r"(b0), "r"(b1));
}
__device__ __forceinline__ uint32_t pkbf(float a, float b) {
    __nv_bfloat16 ha = __float2bfloat16(a), hb = __float2bfloat16(b);
    return (uint32_t)__bfloat16_as_ushort(ha) | ((uint32_t)__bfloat16_as_ushort(hb) << 16);
}

// 3-pass hi/lo bf16 GEMM: warp tile 64x32, frags m4 x n4, K=128, accumulate into acc
__device__ __forceinline__ void gemm3pass(uint32_t Ah, uint32_t Al, uint32_t Bh, uint32_t Bl,
                                          int wm0, int wn0, int lane, float acc[4][4][4]) {
    int ar  = (lane & 7) | (((lane >> 3) & 1) << 3);
    int akc = lane >> 4;
    int rbA[4], rxA[4];
    #pragma unroll
    for (int mf = 0; mf < 4; mf++) {
        int r = wm0 + mf * 16 + ar;
        rbA[mf] = r * 256; rxA[mf] = r & 7;
    }
    int bnh = (lane >> 4) & 1, bkc = (lane >> 3) & 1;
    int rbB[2], rxB[2];
    #pragma unroll
    for (int p = 0; p < 2; p++) {
        int r = wn0 + p * 16 + bnh * 8 + (lane & 7);
        rbB[p] = r * 256; rxB[p] = r & 7;
    }
    #pragma unroll
    for (int pass = 0; pass < 3; pass++) {
        uint32_t Ab = (pass == 1) ? Al : Ah;
        uint32_t Bb = (pass == 2) ? Bl : Bh;
        #pragma unroll
        for (int ks = 0; ks < 8; ks++) {
            int kc2 = ks << 1;
            uint32_t a[4][4], b[2][4];
            #pragma unroll
            for (int mf = 0; mf < 4; mf++)
                ldsm4(a[mf], Ab + rbA[mf] + (((kc2 + akc) ^ rxA[mf]) << 4));
            #pragma unroll
            for (int p = 0; p < 2; p++)
                ldsm4(b[p], Bb + rbB[p] + (((kc2 + bkc) ^ rxB[p]) << 4));
            #pragma unroll
            for (int mf = 0; mf < 4; mf++)
                #pragma unroll
                for (int nf = 0; nf < 4; nf++)
                    mma16816(acc[mf][nf], a[mf], b[nf >> 1][(nf & 1) * 2], b[nf >> 1][(nf & 1) * 2 + 1]);
        }
    }
}
// store fragments to staged D [rows][stride 132]
__device__ __forceinline__ void stageD(float* Dst, float acc[4][4][4], int wm0, int wn0, int lane) {
    int rr = lane >> 2, cc = (lane & 3) << 1;
    #pragma unroll
    for (int mf = 0; mf < 4; mf++)
        #pragma unroll
        for (int nf = 0; nf < 4; nf++) {
            int r = wm0 + mf * 16 + rr, c = wn0 + nf * 8 + cc;
            *(float2*)&Dst[r * 132 + c]       = make_float2(acc[mf][nf][0], acc[mf][nf][1]);
            *(float2*)&Dst[(r + 8) * 132 + c] = make_float2(acc[mf][nf][2], acc[mf][nf][3]);
        }
}

// ---------------- K1: per-t emb BN stats via exact x-moments ----------------
__global__ void k_emb_stats(const float* __restrict__ x, const float* __restrict__ W_emb,
                            const float* __restrict__ b_emb, const float* __restrict__ gamma,
                            const float* __restrict__ beta) {
    int t = blockIdx.x, tid = threadIdx.x;
    float m0 = 0.f, m1 = 0.f, m00 = 0.f, m11 = 0.f, m01 = 0.f;
    for (int b = tid; b < Bsz; b += 256) {
        size_t xi = ((size_t)b * Tt + t) * 2;
        float x0 = x[xi], x1 = x[xi + 1];
        m0 += x0; m1 += x1; m00 += x0 * x0; m11 += x1 * x1; m01 += x0 * x1;
    }
    const unsigned F = 0xffffffffu;
    #pragma unroll
    for (int o = 16; o; o >>= 1) {
        m0 += __shfl_xor_sync(F, m0, o); m1 += __shfl_xor_sync(F, m1, o);
        m00 += __shfl_xor_sync(F, m00, o); m11 += __shfl_xor_sync(F, m11, o);
        m01 += __shfl_xor_sync(F, m01, o);
    }
    __shared__ float sw[8][5], mom[5];
    int w = tid >> 5, l = tid & 31;
    if (l == 0) { sw[w][0] = m0; sw[w][1] = m1; sw[w][2] = m00; sw[w][3] = m11; sw[w][4] = m01; }
    __syncthreads();
    if (tid < 5) {
        float s = 0.f;
        #pragma unroll
        for (int i = 0; i < 8; i++) s += sw[i][tid];
        mom[tid] = s * (1.0f / Bsz);
    }
    __syncthreads();
    if (tid < 128) {
        float mx0 = mom[0], mx1 = mom[1];
        float vx0 = mom[2] - mx0 * mx0, vx1 = mom[3] - mx1 * mx1, cxy = mom[4] - mx0 * mx1;
        float w0 = W_emb[tid * 2], w1 = W_emb[tid * 2 + 1];
        float mu = w0 * mx0 + w1 * mx1 + b_emb[tid];
        float var = w0 * w0 * vx0 + 2.0f * w0 * w1 * cxy + w1 * w1 * vx1;
        float gr = gamma[tid] * rsqrtf(var + 1e-5f);
        int o = (t * 128 + tid) * 3;
        g_s[o] = gr * w0; g_s[o + 1] = gr * w1;
        g_s[o + 2] = gr * (b_emb[tid] - mu) + beta[tid];
    }
}

// ---------------- K2: build bf16 hi/lo weight images (n' = 4j+gate) ----------------
__global__ void k_prep(const float* __restrict__ Wih, const float* __restrict__ Whh,
                       const float* __restrict__ bih, const float* __restrict__ bhh) {
    int id = blockIdx.x * 256 + threadIdx.x;  // 131072
    int mat = id >> 16, e = id & 65535;
    int np = e >> 7, k = e & 127;
    int src = ((np & 3) * 128 + (np >> 2)) * 128 + k;
    float wv = mat ? Whh[src] : Wih[src];
    __nv_bfloat16 hi = __float2bfloat16(wv);
    __nv_bfloat16 lo = __float2bfloat16(wv - __bfloat162float(hi));
    int off = np * 256 + (((k >> 3) ^ (np & 7)) << 4) + (k & 7) * 2;
    *(__nv_bfloat16*)((mat ? g_whh_h : g_wih_h) + off) = hi;
    *(__nv_bfloat16*)((mat ? g_whh_l : g_wih_l) + off) = lo;
    if (id < 512) {
        int orig = (id & 3) * 128 + (id >> 2);
        g_bias[id] = bih[orig] + bhh[orig];
    }
}

// ---------------- K3: fully fused step ----------------
// gates = e_t@W_ih^T + h@W_hh^T + bias; then LSTM cell + y partials + h repack.
// grid (nc=4, mtile=32), 512 thr, tile M=256 x N=128
#define ST_A1 0           // 64 KB: e_hi then h_hi  (256 rows x 256B)
#define ST_A2 65536       // 64 KB: e_lo then h_lo
#define ST_B1 131072      // 32 KB: W*_hi chunk (128 rows)
#define ST_B2 163840      // 32 KB: W*_lo chunk
#define ST_WS 196608      // 640 floats Wout
#define ST_BS (ST_WS + 2560)   // 128 floats bias chunk
#define ST_SS (ST_BS + 512)    // 384 floats emb affine
#define ST_SMEM (ST_SS + 1536) // 201216 bytes
__global__ void __launch_bounds__(512, 1) k_step(int t, const float* __restrict__ x,
                                                 const float* __restrict__ Wout,
                                                 float* __restrict__ out) {
    extern __shared__ char sm[];
    float* Dst = (float*)sm;  // aliases A/B after mma, stride 132
    float* Ws = (float*)(sm + ST_WS);
    float* bs = (float*)(sm + ST_BS);
    float* ss = (float*)(sm + ST_SS);
    int tid = threadIdx.x;
    int nc = blockIdx.x, m = blockIdx.y, b0 = m << 8;
    uint32_t smb = s2u(sm);
    int lane = tid & 31, w = tid >> 5;
    int wm0 = (w >> 2) * 64, wn0 = (w & 3) * 32;

    for (int i = tid; i < 640; i += 512) Ws[i] = Wout[i];
    if (tid < 384) ss[tid] = g_s[t * 384 + tid];
    if (tid < 128) bs[tid] = g_bias[nc * 128 + tid];
    __syncthreads();   // ss must be fully written before the e-image build (R5 bug)

    // --- phase 1: build e image (A) + load W_ih chunk (B) ---
    {
        int row = tid >> 1, kh = tid & 1;
        size_t xi = ((size_t)(b0 + row) * Tt + t) * 2;
        float x0 = x[xi], x1 = x[xi + 1];
        #pragma unroll
        for (int ch = 0; ch < 8; ch++) {
            uint32_t wh[4], wl[4];
            #pragma unroll
            for (int q = 0; q < 4; q++) {
                int k = kh * 64 + ch * 8 + q * 2;
                float e0 = fmaxf(fmaf(ss[k * 3], x0, fmaf(ss[k * 3 + 1], x1, ss[k * 3 + 2])), 0.f);
                float e1 = fmaxf(fmaf(ss[k * 3 + 3], x0, fmaf(ss[k * 3 + 4], x1, ss[k * 3 + 5])), 0.f);
                __nv_bfloat16 h0 = __float2bfloat16(e0), h1 = __float2bfloat16(e1);
                float r0 = e0 - __bfloat162float(h0), r1 = e1 - __bfloat162float(h1);
                wh[q] = (uint32_t)__bfloat16_as_ushort(h0) | ((uint32_t)__bfloat16_as_ushort(h1) << 16);
                wl[q] = pkbf(r0, r1);
            }
            int off = swz(row, kh * 8 + ch);
            *(uint4*)(sm + ST_A1 + off) = make_uint4(wh[0], wh[1], wh[2], wh[3]);
            *(uint4*)(sm + ST_A2 + off) = make_uint4(wl[0], wl[1], wl[2], wl[3]);
        }
        const uint4* bh = (const uint4*)(g_wih_h + nc * 32768);
        const uint4* bl = (const uint4*)(g_wih_l + nc * 32768);
        uint4* db = (uint4*)(sm + ST_B1);
        uint4* dl = (uint4*)(sm + ST_B2);
        for (int i = tid; i < 2048; i += 512) { db[i] = bh[i]; dl[i] = bl[i]; }
    }
    __syncthreads();

    float acc[4][4][4];
    #pragma unroll
    for (int i = 0; i < 4; i++)
        #pragma unroll
        for (int j = 0; j < 4; j++)
            #pragma unroll
            for (int q = 0; q < 4; q++) acc[i][j][q] = 0.f;
    gemm3pass(smb + ST_A1, smb + ST_A2, smb + ST_B1, smb + ST_B2, wm0, wn0, lane, acc);

    // --- phase 2: reload A <- h image, B <- W_hh chunk; accumulate ---
    if (t > 0) {
        __syncthreads();   // all warps done reading e / W_ih
        int p = t & 1;
        const uint4* ah = (const uint4*)(g_himg[p][0] + (size_t)b0 * 256);
        const uint4* al = (const uint4*)(g_himg[p][1] + (size_t)b0 * 256);
        uint4* da = (uint4*)(sm + ST_A1);
        uint4* dl2 = (uint4*)(sm + ST_A2);
        for (int i = tid; i < 4096; i += 512) { da[i] = ah[i]; dl2[i] = al[i]; }
        const uint4* bh = (const uint4*)(g_whh_h + nc * 32768);
        const uint4* bl = (const uint4*)(g_whh_l + nc * 32768);
        uint4* eb = (uint4*)(sm + ST_B1);
        uint4* el = (uint4*)(sm + ST_B2);
        for (int i = tid; i < 2048; i += 512) { eb[i] = bh[i]; el[i] = bl[i]; }
        __syncthreads();
        gemm3pass(smb + ST_A1, smb + ST_A2, smb + ST_B1, smb + ST_B2, wm0, wn0, lane, acc);
    }
    __syncthreads();       // done reading A/B before Dst alias write
    stageD(Dst, acc, wm0, wn0, lane);
    __syncthreads();

    // --- cell: thread -> (row = tid>>1, 16 j's at jh*16) ---
    int row = tid >> 1, jh = tid & 1;
    int rg = b0 + row;
    int jg0 = nc * 32 + jh * 16;
    float cold[16];
    if (t > 0) {
        #pragma unroll
        for (int q = 0; q < 4; q++)
            *(float4*)&cold[q * 4] = *(const float4*)&g_c[(size_t)rg * 128 + jg0 + q * 4];
    } else {
        #pragma unroll
        for (int q = 0; q < 16; q++) cold[q] = 0.f;
    }
    float y0 = 0.f, y1 = 0.f, y2 = 0.f, y3 = 0.f, y4 = 0.f;
    float hnv[16], cnv[16];
    unsigned short hs[16], lsv[16];
    #pragma unroll
    for (int jj = 0; jj < 16; jj++) {
        int jloc = jh * 16 + jj;
        float4 g4 = *(float4*)&Dst[row * 132 + (jloc << 2)];
        float4 bv = *(float4*)&bs[jloc << 2];
        float gi = g4.x + bv.x, gf = g4.y + bv.y, gg = g4.z + bv.z, go = g4.w + bv.w;
        float si = __fdividef(1.f, 1.f + __expf(-gi));
        float sf = __fdividef(1.f, 1.f + __expf(-gf));
        float tg = __fdividef(2.f, 1.f + __expf(-2.f * gg)) - 1.f;
        float so = __fdividef(1.f, 1.f + __expf(-go));
        float cn = sf * cold[jj] + si * tg;
        float tc = __fdividef(2.f, 1.f + __expf(-2.f * cn)) - 1.f;
        float hn = so * tc;
        cnv[jj] = cn; hnv[jj] = hn;
        __nv_bfloat16 hb = __float2bfloat16(hn);
        hs[jj] = __bfloat16_as_ushort(hb);
        lsv[jj] = __bfloat16_as_ushort(__float2bfloat16(hn - __bfloat162float(hb)));
        int jg = jg0 + jj;
        y0 = fmaf(hn, Ws[jg], y0);
        y1 = fmaf(hn, Ws[128 + jg], y1);
        y2 = fmaf(hn, Ws[256 + jg], y2);
        y3 = fmaf(hn, Ws[384 + jg], y3);
        y4 = fmaf(hn, Ws[512 + jg], y4);
    }
    #pragma unroll
    for (int q = 0; q < 4; q++)
        *(float4*)&g_c[(size_t)rg * 128 + jg0 + q * 4] = *(float4*)&cnv[q * 4];
    // pack h image for next step, parity (t&1)^1
    int p1 = (t & 1) ^ 1;
    #pragma unroll
    for (int ch = 0; ch < 2; ch++) {
        uint32_t wh[4], wl[4];
        #pragma unroll
        for (int q = 0; q < 4; q++) {
            wh[q] = (uint32_t)hs[ch * 8 + q * 2] | ((uint32_t)hs[ch * 8 + q * 2 + 1] << 16);
            wl[q] = (uint32_t)lsv[ch * 8 + q * 2] | ((uint32_t)lsv[ch * 8 + q * 2 + 1] << 16);
        }
        int off = swz(rg, (jg0 >> 3) + ch);
        *(uint4*)(g_himg[p1][0] + off) = make_uint4(wh[0], wh[1], wh[2], wh[3]);
        *(uint4*)(g_himg[p1][1] + off) = make_uint4(wl[0], wl[1], wl[2], wl[3]);
    }
    const unsigned F = 0xffffffffu;
    y0 += __shfl_xor_sync(F, y0, 1); y1 += __shfl_xor_sync(F, y1, 1);
    y2 += __shfl_xor_sync(F, y2, 1); y3 += __shfl_xor_sync(F, y3, 1);
    y4 += __shfl_xor_sync(F, y4, 1);
    if (!jh) {
        size_t yb = ((size_t)nc * 640 + t * 5) * 8192 + rg;
        g_ypart[yb] = y0; g_ypart[yb + 8192] = y1; g_ypart[yb + 16384] = y2;
        g_ypart[yb + 24576] = y3; g_ypart[yb + 32768] = y4;
    }
    if (t == 127) {
        #pragma unroll
        for (int q = 0; q < 4; q++) {
            *(float4*)&out[OFF_H + (size_t)rg * 128 + jg0 + q * 4] = *(float4*)&hnv[q * 4];
            *(float4*)&out[OFF_C + (size_t)rg * 128 + jg0 + q * 4] = *(float4*)&cnv[q * 4];
        }
    }
}

// ---------------- K5/K6: output BN over y partials ----------------
__global__ void k_ystats() {
    int tf = blockIdx.x, tid = threadIdx.x;
    float s = 0.f, q = 0.f;
    for (int b = tid; b < Bsz; b += 256) {
        float v = g_ypart[(size_t)tf * 8192 + b]
                + g_ypart[(size_t)640 * 8192 + (size_t)tf * 8192 + b]
                + g_ypart[(size_t)2 * 640 * 8192 + (size_t)tf * 8192 + b]
                + g_ypart[(size_t)3 * 640 * 8192 + (size_t)tf * 8192 + b];
        s += v; q += v * v;
    }
    const unsigned F = 0xffffffffu;
    #pragma unroll
    for (int o = 16; o; o >>= 1) { s += __shfl_xor_sync(F, s, o); q += __shfl_xor_sync(F, q, o); }
    __shared__ float sws[8], swq[8];
    int w = tid >> 5;
    if ((tid & 31) == 0) { sws[w] = s; swq[w] = q; }
    __syncthreads();
    if (tid == 0) {
        float S = 0.f, Q = 0.f;
        #pragma unroll
        for (int i = 0; i < 8; i++) { S += sws[i]; Q += swq[i]; }
        float mean = S * (1.0f / Bsz);
        g_ymean[tf] = mean;
        g_yrstd[tf] = rsqrtf(Q * (1.0f / Bsz) - mean * mean + 1e-5f);
    }
}
__global__ void k_ynorm(const float* __restrict__ gamma, const float* __restrict__ beta,
                        float* __restrict__ out) {
    size_t i = (size_t)blockIdx.x * 256 + threadIdx.x;
    if (i >= (size_t)Bsz * Tt * Do) return;
    size_t b = i / 640;
    int r = (int)(i % 640);
    int f = r % 5;
    int tf = r;
    float v = g_ypart[(size_t)tf * 8192 + b]
            + g_ypart[(size_t)640 * 8192 + (size_t)tf * 8192 + b]
            + g_ypart[(size_t)2 * 640 * 8192 + (size_t)tf * 8192 + b]
            + g_ypart[(size_t)3 * 640 * 8192 + (size_t)tf * 8192 + b];
    out[i] = gamma[f] * (v - g_ymean[tf]) * g_yrstd[tf] + beta[f];
}

// ---------------- launch ----------------
extern "C" void kernel_launch(void* const* d_in, const int* in_sizes, int n_in,
                              void* d_out, int out_size) {
    const float* x         = (const float*)d_in[0];
    const float* W_emb     = (const float*)d_in[1];
    const float* b_emb     = (const float*)d_in[2];
    const float* gamma_emb = (const float*)d_in[3];
    const float* beta_emb  = (const float*)d_in[4];
    const float* W_ih      = (const float*)d_in[5];
    const float* b_ih      = (const float*)d_in[6];
    const float* W_hh      = (const float*)d_in[7];
    const float* b_hh      = (const float*)d_in[8];
    const float* W_out     = (const float*)d_in[9];
    // d_in[10] = b_out: cancels exactly inside the output BatchNorm.
    const float* gamma_out = (const float*)d_in[11];
    const float* beta_out  = (const float*)d_in[12];
    float* out = (float*)d_out;

    cudaFuncSetAttribute(k_step, cudaFuncAttributeMaxDynamicSharedMemorySize, ST_SMEM);

    k_emb_stats<<<Tt, 256>>>(x, W_emb, b_emb, gamma_emb, beta_emb);
    k_prep<<<512, 256>>>(W_ih, W_hh, b_ih, b_hh);
    for (int t = 0; t < Tt; t++)
        k_step<<<dim3(4, 32), 512, ST_SMEM>>>(t, x, W_out, out);
    k_ystats<<<Tt * Do, 256>>>();
    int n = Bsz * Tt * Do;
    k_ynorm<<<(n + 255) / 256, 256>>>(gamma_out, beta_out, out);
}

// round 7
// speedup vs baseline: 1.7702x; 1.0012x over previous
#include <cuda_runtime.h>
#include <cuda_bf16.h>
#include <math.h>
#include <stdint.h>

#define Bsz 8192
#define Tt  128
#define Do  5
#define OFF_H ((size_t)Bsz * Tt * Do)
#define OFF_C (OFF_H + (size_t)Bsz * 128)

// ---------------- device scratch ----------------
__device__ float g_c[(size_t)Bsz * 128];           // c state [row][j]
__device__ float g_ypart[(size_t)4 * 640 * 8192];  // y partials [nc][t*5+f][row]
__device__ float g_s[Tt * 128 * 3];                // folded emb-BN affine
__device__ float g_bias[512];                      // b_ih+b_hh permuted to n'
__device__ float g_ymean[Tt * Do];
__device__ float g_yrstd[Tt * Do];
// bf16 operand images, row-major 256B rows with 16B-chunk XOR swizzle
__device__ __align__(16) char g_wih_h[512 * 256];
__device__ __align__(16) char g_wih_l[512 * 256];
__device__ __align__(16) char g_whh_h[512 * 256];
__device__ __align__(16) char g_whh_l[512 * 256];
__device__ __align__(16) char g_himg[2][2][8192 * 256];  // [parity][hi/lo]

// swizzled byte offset of 16B chunk kc in row
__device__ __forceinline__ int swz(int row, int kc) {
    return row * 256 + ((kc ^ (row & 7)) << 4);
}
__device__ __forceinline__ uint32_t s2u(const void* p) {
    uint32_t a;
    asm("{ .reg .u64 t; cvta.to.shared.u64 t, %1; cvt.u32.u64 %0, t; }" : "=r"(a) : "l"(p));
    return a;
}
__device__ __forceinline__ void ldsm4(uint32_t r[4], uint32_t a) {
    asm volatile("ldmatrix.sync.aligned.m8n8.x4.shared.b16 {%0,%1,%2,%3}, [%4];"
        : "=r"(r[0]), "=r"(r[1]), "=r"(r[2]), "=r"(r[3]) : "r"(a));
}
__device__ __forceinline__ void mma16816(float d[4], const uint32_t a[4], uint32_t b0, uint32_t b1) {
    asm volatile("mma.sync.aligned.m16n8k16.row.col.f32.bf16.bf16.f32 "
        "{%0,%1,%2,%3}, {%4,%5,%6,%7}, {%8,%9}, {%0,%1,%2,%3};"
        : "+f"(d[0]), "+f"(d[1]), "+f"(d[2]), "+f"(d[3])
        : "r"(a[0]), "r"(a[1]), "r"(a[2]), "r"(a[3]), "r"(b0), "r"(b1));
}
__device__ __forceinline__ uint32_t pkbf(float a, float b) {
    __nv_bfloat16 ha = __float2bfloat16(a), hb = __float2bfloat16(b);
    return (uint32_t)__bfloat16_as_ushort(ha) | ((uint32_t)__bfloat16_as_ushort(hb) << 16);
}

// 3-pass hi/lo bf16 GEMM: warp tile 64x32, frags m4 x n4, K=128, accumulate into acc
__device__ __forceinline__ void gemm3pass(uint32_t Ah, uint32_t Al, uint32_t Bh, uint32_t Bl,
                                          int wm0, int wn0, int lane, float acc[4][4][4]) {
    int ar  = (lane & 7) | (((lane >> 3) & 1) << 3);
    int akc = lane >> 4;
    int rbA[4], rxA[4];
    #pragma unroll
    for (int mf = 0; mf < 4; mf++) {
        int r = wm0 + mf * 16 + ar;
        rbA[mf] = r * 256; rxA[mf] = r & 7;
    }
    int bnh = (lane >> 4) & 1, bkc = (lane >> 3) & 1;
    int rbB[2], rxB[2];
    #pragma unroll
    for (int p = 0; p < 2; p++) {
        int r = wn0 + p * 16 + bnh * 8 + (lane & 7);
        rbB[p] = r * 256; rxB[p] = r & 7;
    }
    #pragma unroll
    for (int pass = 0; pass < 3; pass++) {
        uint32_t Ab = (pass == 1) ? Al : Ah;
        uint32_t Bb = (pass == 2) ? Bl : Bh;
        #pragma unroll
        for (int ks = 0; ks < 8; ks++) {
            int kc2 = ks << 1;
            uint32_t a[4][4], b[2][4];
            #pragma unroll
            for (int mf = 0; mf < 4; mf++)
                ldsm4(a[mf], Ab + rbA[mf] + (((kc2 + akc) ^ rxA[mf]) << 4));
            #pragma unroll
            for (int p = 0; p < 2; p++)
                ldsm4(b[p], Bb + rbB[p] + (((kc2 + bkc) ^ rxB[p]) << 4));
            #pragma unroll
            for (int mf = 0; mf < 4; mf++)
                #pragma unroll
                for (int nf = 0; nf < 4; nf++)
                    mma16816(acc[mf][nf], a[mf], b[nf >> 1][(nf & 1) * 2], b[nf >> 1][(nf & 1) * 2 + 1]);
        }
    }
}
// store fragments to staged D [rows][stride 132]
__device__ __forceinline__ void stageD(float* Dst, float acc[4][4][4], int wm0, int wn0, int lane) {
    int rr = lane >> 2, cc = (lane & 3) << 1;
    #pragma unroll
    for (int mf = 0; mf < 4; mf++)
        #pragma unroll
        for (int nf = 0; nf < 4; nf++) {
            int r = wm0 + mf * 16 + rr, c = wn0 + nf * 8 + cc;
            *(float2*)&Dst[r * 132 + c]       = make_float2(acc[mf][nf][0], acc[mf][nf][1]);
            *(float2*)&Dst[(r + 8) * 132 + c] = make_float2(acc[mf][nf][2], acc[mf][nf][3]);
        }
}

// ---------------- K1: per-t emb BN stats via exact x-moments ----------------
__global__ void k_emb_stats(const float* __restrict__ x, const float* __restrict__ W_emb,
                            const float* __restrict__ b_emb, const float* __restrict__ gamma,
                            const float* __restrict__ beta) {
    int t = blockIdx.x, tid = threadIdx.x;
    float m0 = 0.f, m1 = 0.f, m00 = 0.f, m11 = 0.f, m01 = 0.f;
    for (int b = tid; b < Bsz; b += 256) {
        size_t xi = ((size_t)b * Tt + t) * 2;
        float x0 = x[xi], x1 = x[xi + 1];
        m0 += x0; m1 += x1; m00 += x0 * x0; m11 += x1 * x1; m01 += x0 * x1;
    }
    const unsigned F = 0xffffffffu;
    #pragma unroll
    for (int o = 16; o; o >>= 1) {
        m0 += __shfl_xor_sync(F, m0, o); m1 += __shfl_xor_sync(F, m1, o);
        m00 += __shfl_xor_sync(F, m00, o); m11 += __shfl_xor_sync(F, m11, o);
        m01 += __shfl_xor_sync(F, m01, o);
    }
    __shared__ float sw[8][5], mom[5];
    int w = tid >> 5, l = tid & 31;
    if (l == 0) { sw[w][0] = m0; sw[w][1] = m1; sw[w][2] = m00; sw[w][3] = m11; sw[w][4] = m01; }
    __syncthreads();
    if (tid < 5) {
        float s = 0.f;
        #pragma unroll
        for (int i = 0; i < 8; i++) s += sw[i][tid];
        mom[tid] = s * (1.0f / Bsz);
    }
    __syncthreads();
    if (tid < 128) {
        float mx0 = mom[0], mx1 = mom[1];
        float vx0 = mom[2] - mx0 * mx0, vx1 = mom[3] - mx1 * mx1, cxy = mom[4] - mx0 * mx1;
        float w0 = W_emb[tid * 2], w1 = W_emb[tid * 2 + 1];
        float mu = w0 * mx0 + w1 * mx1 + b_emb[tid];
        float var = w0 * w0 * vx0 + 2.0f * w0 * w1 * cxy + w1 * w1 * vx1;
        float gr = gamma[tid] * rsqrtf(var + 1e-5f);
        int o = (t * 128 + tid) * 3;
        g_s[o] = gr * w0; g_s[o + 1] = gr * w1;
        g_s[o + 2] = gr * (b_emb[tid] - mu) + beta[tid];
    }
}

// ---------------- K2: build bf16 hi/lo weight images (n' = 4j+gate) ----------------
__global__ void k_prep(const float* __restrict__ Wih, const float* __restrict__ Whh,
                       const float* __restrict__ bih, const float* __restrict__ bhh) {
    int id = blockIdx.x * 256 + threadIdx.x;  // 131072
    int mat = id >> 16, e = id & 65535;
    int np = e >> 7, k = e & 127;
    int src = ((np & 3) * 128 + (np >> 2)) * 128 + k;
    float wv = mat ? Whh[src] : Wih[src];
    __nv_bfloat16 hi = __float2bfloat16(wv);
    __nv_bfloat16 lo = __float2bfloat16(wv - __bfloat162float(hi));
    int off = np * 256 + (((k >> 3) ^ (np & 7)) << 4) + (k & 7) * 2;
    *(__nv_bfloat16*)((mat ? g_whh_h : g_wih_h) + off) = hi;
    *(__nv_bfloat16*)((mat ? g_whh_l : g_wih_l) + off) = lo;
    if (id < 512) {
        int orig = (id & 3) * 128 + (id >> 2);
        g_bias[id] = bih[orig] + bhh[orig];
    }
}

// ---------------- K3: fully fused step ----------------
// gates = e_t@W_ih^T + h@W_hh^T + bias; then LSTM cell + y partials + h repack.
// grid (nc=4, mtile=32), 512 thr, tile M=256 x N=128
#define ST_A1 0           // 64 KB: e_hi then h_hi  (256 rows x 256B)
#define ST_A2 65536       // 64 KB: e_lo then h_lo
#define ST_B1 131072      // 32 KB: W*_hi chunk (128 rows)
#define ST_B2 163840      // 32 KB: W*_lo chunk
#define ST_WS 196608      // 640 floats Wout
#define ST_BS (ST_WS + 2560)   // 128 floats bias chunk
#define ST_SS (ST_BS + 512)    // 384 floats emb affine
#define ST_SMEM (ST_SS + 1536) // 201216 bytes
__global__ void __launch_bounds__(512, 1) k_step(int t, const float* __restrict__ x,
                                                 const float* __restrict__ Wout,
                                                 float* __restrict__ out) {
    extern __shared__ char sm[];
    float* Dst = (float*)sm;  // aliases A/B after mma, stride 132
    float* Ws = (float*)(sm + ST_WS);
    float* bs = (float*)(sm + ST_BS);
    float* ss = (float*)(sm + ST_SS);
    int tid = threadIdx.x;
    int nc = blockIdx.x, m = blockIdx.y, b0 = m << 8;
    uint32_t smb = s2u(sm);
    int lane = tid & 31, w = tid >> 5;
    int wm0 = (w >> 2) * 64, wn0 = (w & 3) * 32;

    for (int i = tid; i < 640; i += 512) Ws[i] = Wout[i];
    if (tid < 384) ss[tid] = g_s[t * 384 + tid];
    if (tid < 128) bs[tid] = g_bias[nc * 128 + tid];
    __syncthreads();   // ss must be fully written before the e-image build (R5 bug)

    // --- phase 1: build e image (A) + load W_ih chunk (B) ---
    {
        int row = tid >> 1, kh = tid & 1;
        size_t xi = ((size_t)(b0 + row) * Tt + t) * 2;
        float x0 = x[xi], x1 = x[xi + 1];
        #pragma unroll
        for (int ch = 0; ch < 8; ch++) {
            uint32_t wh[4], wl[4];
            #pragma unroll
            for (int q = 0; q < 4; q++) {
                int k = kh * 64 + ch * 8 + q * 2;
                float e0 = fmaxf(fmaf(ss[k * 3], x0, fmaf(ss[k * 3 + 1], x1, ss[k * 3 + 2])), 0.f);
                float e1 = fmaxf(fmaf(ss[k * 3 + 3], x0, fmaf(ss[k * 3 + 4], x1, ss[k * 3 + 5])), 0.f);
                __nv_bfloat16 h0 = __float2bfloat16(e0), h1 = __float2bfloat16(e1);
                float r0 = e0 - __bfloat162float(h0), r1 = e1 - __bfloat162float(h1);
                wh[q] = (uint32_t)__bfloat16_as_ushort(h0) | ((uint32_t)__bfloat16_as_ushort(h1) << 16);
                wl[q] = pkbf(r0, r1);
            }
            int off = swz(row, kh * 8 + ch);
            *(uint4*)(sm + ST_A1 + off) = make_uint4(wh[0], wh[1], wh[2], wh[3]);
            *(uint4*)(sm + ST_A2 + off) = make_uint4(wl[0], wl[1], wl[2], wl[3]);
        }
        const uint4* bh = (const uint4*)(g_wih_h + nc * 32768);
        const uint4* bl = (const uint4*)(g_wih_l + nc * 32768);
        uint4* db = (uint4*)(sm + ST_B1);
        uint4* dl = (uint4*)(sm + ST_B2);
        for (int i = tid; i < 2048; i += 512) { db[i] = bh[i]; dl[i] = bl[i]; }
    }
    __syncthreads();

    float acc[4][4][4];
    #pragma unroll
    for (int i = 0; i < 4; i++)
        #pragma unroll
        for (int j = 0; j < 4; j++)
            #pragma unroll
            for (int q = 0; q < 4; q++) acc[i][j][q] = 0.f;
    gemm3pass(smb + ST_A1, smb + ST_A2, smb + ST_B1, smb + ST_B2, wm0, wn0, lane, acc);

    // --- phase 2: reload A <- h image, B <- W_hh chunk; accumulate ---
    if (t > 0) {
        __syncthreads();   // all warps done reading e / W_ih
        int p = t & 1;
        const uint4* ah = (const uint4*)(g_himg[p][0] + (size_t)b0 * 256);
        const uint4* al = (const uint4*)(g_himg[p][1] + (size_t)b0 * 256);
        uint4* da = (uint4*)(sm + ST_A1);
        uint4* dl2 = (uint4*)(sm + ST_A2);
        for (int i = tid; i < 4096; i += 512) { da[i] = ah[i]; dl2[i] = al[i]; }
        const uint4* bh = (const uint4*)(g_whh_h + nc * 32768);
        const uint4* bl = (const uint4*)(g_whh_l + nc * 32768);
        uint4* eb = (uint4*)(sm + ST_B1);
        uint4* el = (uint4*)(sm + ST_B2);
        for (int i = tid; i < 2048; i += 512) { eb[i] = bh[i]; el[i] = bl[i]; }
        __syncthreads();
        gemm3pass(smb + ST_A1, smb + ST_A2, smb + ST_B1, smb + ST_B2, wm0, wn0, lane, acc);
    }
    __syncthreads();       // done reading A/B before Dst alias write
    stageD(Dst, acc, wm0, wn0, lane);
    __syncthreads();

    // --- cell: thread -> (row = tid>>1, 16 j's at jh*16) ---
    int row = tid >> 1, jh = tid & 1;
    int rg = b0 + row;
    int jg0 = nc * 32 + jh * 16;
    float cold[16];
    if (t > 0) {
        #pragma unroll
        for (int q = 0; q < 4; q++)
            *(float4*)&cold[q * 4] = *(const float4*)&g_c[(size_t)rg * 128 + jg0 + q * 4];
    } else {
        #pragma unroll
        for (int q = 0; q < 16; q++) cold[q] = 0.f;
    }
    float y0 = 0.f, y1 = 0.f, y2 = 0.f, y3 = 0.f, y4 = 0.f;
    float hnv[16], cnv[16];
    unsigned short hs[16], lsv[16];
    #pragma unroll
    for (int jj = 0; jj < 16; jj++) {
        int jloc = jh * 16 + jj;
        float4 g4 = *(float4*)&Dst[row * 132 + (jloc << 2)];
        float4 bv = *(float4*)&bs[jloc << 2];
        float gi = g4.x + bv.x, gf = g4.y + bv.y, gg = g4.z + bv.z, go = g4.w + bv.w;
        float si = __fdividef(1.f, 1.f + __expf(-gi));
        float sf = __fdividef(1.f, 1.f + __expf(-gf));
        float tg = __fdividef(2.f, 1.f + __expf(-2.f * gg)) - 1.f;
        float so = __fdividef(1.f, 1.f + __expf(-go));
        float cn = sf * cold[jj] + si * tg;
        float tc = __fdividef(2.f, 1.f + __expf(-2.f * cn)) - 1.f;
        float hn = so * tc;
        cnv[jj] = cn; hnv[jj] = hn;
        __nv_bfloat16 hb = __float2bfloat16(hn);
        hs[jj] = __bfloat16_as_ushort(hb);
        lsv[jj] = __bfloat16_as_ushort(__float2bfloat16(hn - __bfloat162float(hb)));
        int jg = jg0 + jj;
        y0 = fmaf(hn, Ws[jg], y0);
        y1 = fmaf(hn, Ws[128 + jg], y1);
        y2 = fmaf(hn, Ws[256 + jg], y2);
        y3 = fmaf(hn, Ws[384 + jg], y3);
        y4 = fmaf(hn, Ws[512 + jg], y4);
    }
    #pragma unroll
    for (int q = 0; q < 4; q++)
        *(float4*)&g_c[(size_t)rg * 128 + jg0 + q * 4] = *(float4*)&cnv[q * 4];
    // pack h image for next step, parity (t&1)^1
    int p1 = (t & 1) ^ 1;
    #pragma unroll
    for (int ch = 0; ch < 2; ch++) {
        uint32_t wh[4], wl[4];
        #pragma unroll
        for (int q = 0; q < 4; q++) {
            wh[q] = (uint32_t)hs[ch * 8 + q * 2] | ((uint32_t)hs[ch * 8 + q * 2 + 1] << 16);
            wl[q] = (uint32_t)lsv[ch * 8 + q * 2] | ((uint32_t)lsv[ch * 8 + q * 2 + 1] << 16);
        }
        int off = swz(rg, (jg0 >> 3) + ch);
        *(uint4*)(g_himg[p1][0] + off) = make_uint4(wh[0], wh[1], wh[2], wh[3]);
        *(uint4*)(g_himg[p1][1] + off) = make_uint4(wl[0], wl[1], wl[2], wl[3]);
    }
    const unsigned F = 0xffffffffu;
    y0 += __shfl_xor_sync(F, y0, 1); y1 += __shfl_xor_sync(F, y1, 1);
    y2 += __shfl_xor_sync(F, y2, 1); y3 += __shfl_xor_sync(F, y3, 1);
    y4 += __shfl_xor_sync(F, y4, 1);
    if (!jh) {
        size_t yb = ((size_t)nc * 640 + t * 5) * 8192 + rg;
        g_ypart[yb] = y0; g_ypart[yb + 8192] = y1; g_ypart[yb + 16384] = y2;
        g_ypart[yb + 24576] = y3; g_ypart[yb + 32768] = y4;
    }
    if (t == 127) {
        #pragma unroll
        for (int q = 0; q < 4; q++) {
            *(float4*)&out[OFF_H + (size_t)rg * 128 + jg0 + q * 4] = *(float4*)&hnv[q * 4];
            *(float4*)&out[OFF_C + (size_t)rg * 128 + jg0 + q * 4] = *(float4*)&cnv[q * 4];
        }
    }
}

// ---------------- K5/K6: output BN over y partials ----------------
__global__ void k_ystats() {
    int tf = blockIdx.x, tid = threadIdx.x;
    float s = 0.f, q = 0.f;
    for (int b = tid; b < Bsz; b += 256) {
        float v = g_ypart[(size_t)tf * 8192 + b]
                + g_ypart[(size_t)640 * 8192 + (size_t)tf * 8192 + b]
                + g_ypart[(size_t)2 * 640 * 8192 + (size_t)tf * 8192 + b]
                + g_ypart[(size_t)3 * 640 * 8192 + (size_t)tf * 8192 + b];
        s += v; q += v * v;
    }
    const unsigned F = 0xffffffffu;
    #pragma unroll
    for (int o = 16; o; o >>= 1) { s += __shfl_xor_sync(F, s, o); q += __shfl_xor_sync(F, q, o); }
    __shared__ float sws[8], swq[8];
    int w = tid >> 5;
    if ((tid & 31) == 0) { sws[w] = s; swq[w] = q; }
    __syncthreads();
    if (tid == 0) {
        float S = 0.f, Q = 0.f;
        #pragma unroll
        for (int i = 0; i < 8; i++) { S += sws[i]; Q += swq[i]; }
        float mean = S * (1.0f / Bsz);
        g_ymean[tf] = mean;
        g_yrstd[tf] = rsqrtf(Q * (1.0f / Bsz) - mean * mean + 1e-5f);
    }
}
__global__ void k_ynorm(const float* __restrict__ gamma, const float* __restrict__ beta,
                        float* __restrict__ out) {
    size_t i = (size_t)blockIdx.x * 256 + threadIdx.x;
    if (i >= (size_t)Bsz * Tt * Do) return;
    size_t b = i / 640;
    int r = (int)(i % 640);
    int f = r % 5;
    int tf = r;
    float v = g_ypart[(size_t)tf * 8192 + b]
            + g_ypart[(size_t)640 * 8192 + (size_t)tf * 8192 + b]
            + g_ypart[(size_t)2 * 640 * 8192 + (size_t)tf * 8192 + b]
            + g_ypart[(size_t)3 * 640 * 8192 + (size_t)tf * 8192 + b];
    out[i] = gamma[f] * (v - g_ymean[tf]) * g_yrstd[tf] + beta[f];
}

// ---------------- launch ----------------
extern "C" void kernel_launch(void* const* d_in, const int* in_sizes, int n_in,
                              void* d_out, int out_size) {
    const float* x         = (const float*)d_in[0];
    const float* W_emb     = (const float*)d_in[1];
    const float* b_emb     = (const float*)d_in[2];
    const float* gamma_emb = (const float*)d_in[3];
    const float* beta_emb  = (const float*)d_in[4];
    const float* W_ih      = (const float*)d_in[5];
    const float* b_ih      = (const float*)d_in[6];
    const float* W_hh      = (const float*)d_in[7];
    const float* b_hh      = (const float*)d_in[8];
    const float* W_out     = (const float*)d_in[9];
    // d_in[10] = b_out: cancels exactly inside the output BatchNorm.
    const float* gamma_out = (const float*)d_in[11];
    const float* beta_out  = (const float*)d_in[12];
    float* out = (float*)d_out;

    cudaFuncSetAttribute(k_step, cudaFuncAttributeMaxDynamicSharedMemorySize, ST_SMEM);

    k_emb_stats<<<Tt, 256>>>(x, W_emb, b_emb, gamma_emb, beta_emb);
    k_prep<<<512, 256>>>(W_ih, W_hh, b_ih, b_hh);
    for (int t = 0; t < Tt; t++)
        k_step<<<dim3(4, 32), 512, ST_SMEM>>>(t, x, W_out, out);
    k_ystats<<<Tt * Do, 256>>>();
    int n = Bsz * Tt * Do;
    k_ynorm<<<(n + 255) / 256, 256>>>(gamma_out, beta_out, out);
}